// round 13
// baseline (speedup 1.0000x reference)
#include <cuda_runtime.h>
#include <cuda_fp16.h>
#include <cstdint>

// Problem dims
constexpr int NB = 256, NT = 512, NF = 256, NH = 1024, NG = 4096;
constexpr int NKD = NH + NF; // 1280
constexpr int NOUT = 64;

// Persistent step-GEMM tiling (fp16 mma.sync + cp.async.bulk, K-split + frag DB)
constexpr int BM = 64, BN = 128, BK = 128;
constexpr int NKT = NKD / BK;   // 10 (kt 0..7 = h blocks, 8..9 = x blocks)
constexpr int NST = 3;
constexpr int A_BY = BM * BK * 2;        // 16384 B
constexpr int B_BY = BN * BK * 2;        // 32768 B
constexpr int ST_BY = A_BY + B_BY;       // 49152 B
constexpr int ST_H = ST_BY / 2;
constexpr int A_H = A_BY / 2;
constexpr int MERGE_BY = 8 * 32 * 36 * 4;          // 36864 B padded partial buffer
constexpr int SMEM_BYTES = NST * ST_BY + MERGE_BY; // 184320
constexpr int NCTAS = (NB / BM) * (NG / BN);       // 128
constexpr int HSZ = 8 * NB * BK;                   // halves per h buffer
constexpr int NTHREADS = 512;                      // 16 warps, K-split pairs

// per-16 k permutation: position q holds k = PERM[q]
__device__ __constant__ int c_perm[16] = {0,1,8,9, 2,3,10,11, 4,5,12,13, 6,7,14,15};
__device__ __constant__ int c_pinv[16] = {0,1,4,5, 8,9,12,13, 2,3,6,7, 10,11,14,15};

// ---------------- device scratch ----------------
__device__ __half g_MB[(long)10 * NG * BK];      // [kt(10)][n][128] weights
__device__ __half g_xB[(long)NT * 2 * NB * BK];  // [t][kb][b][128] fp16 x blocks
__device__ __half g_h[2 * HSZ];                  // ping-pong hidden, block layout
__device__ float  g_bI[NG];
__device__ float  g_MLP[2048 * NH];
__device__ float  g_cf[NB * NH];
__device__ float  g_hf[NB * NH];
__device__ float  g_y1[NB * NH];
__device__ unsigned g_maskw[NB * 16];
__device__ unsigned g_hcnt[16];                  // [buf][kb] h-block ready counters

// ---------------- helpers ----------------
__device__ __forceinline__ unsigned smem_u32(const void* p) {
    unsigned a;
    asm("{ .reg .u64 t; cvta.to.shared.u64 t, %1; cvt.u32.u64 %0, t; }" : "=r"(a) : "l"(p));
    return a;
}
__device__ __forceinline__ float fex2(float x) {
    float y; asm("ex2.approx.f32 %0, %1;" : "=f"(y) : "f"(x)); return y;
}
__device__ __forceinline__ float frcp(float x) {
    float y; asm("rcp.approx.f32 %0, %1;" : "=f"(y) : "f"(x)); return y;
}
__device__ __forceinline__ float sigmf(float x) {
    return frcp(1.0f + fex2(-1.4426950408889634f * x));
}
__device__ __forceinline__ float tanhfa(float x) {
    return 1.0f - 2.0f * frcp(1.0f + fex2(2.8853900817779268f * x));
}
__device__ __forceinline__ void mma16(float* d, unsigned a0, unsigned a1, unsigned a2,
                                      unsigned a3, unsigned b0, unsigned b1) {
    asm volatile(
        "mma.sync.aligned.m16n8k16.row.col.f32.f16.f16.f32 "
        "{%0,%1,%2,%3}, {%4,%5,%6,%7}, {%8,%9}, {%0,%1,%2,%3};"
        : "+f"(d[0]), "+f"(d[1]), "+f"(d[2]), "+f"(d[3])
        : "r"(a0), "r"(a1), "r"(a2), "r"(a3), "r"(b0), "r"(b1));
}
__device__ __forceinline__ void mbar_init(unsigned mbar, unsigned cnt) {
    asm volatile("mbarrier.init.shared.b64 [%0], %1;" :: "r"(mbar), "r"(cnt) : "memory");
}
__device__ __forceinline__ void mbar_inval(unsigned mbar) {
    asm volatile("mbarrier.inval.shared.b64 [%0];" :: "r"(mbar) : "memory");
}
__device__ __forceinline__ void mbar_expect_tx(unsigned mbar, unsigned bytes) {
    asm volatile("mbarrier.arrive.expect_tx.shared.b64 _, [%0], %1;"
                 :: "r"(mbar), "r"(bytes) : "memory");
}
__device__ __forceinline__ void mbar_wait(unsigned mbar, unsigned parity) {
    asm volatile(
        "{\n\t.reg .pred P;\n"
        "W%=:\n\t"
        "mbarrier.try_wait.parity.acquire.cta.shared::cta.b64 P, [%0], %1, 0x989680;\n\t"
        "@!P bra W%=;\n\t}"
        :: "r"(mbar), "r"(parity) : "memory");
}
__device__ __forceinline__ void bulk_g2s(unsigned dst, const void* src, unsigned bytes,
                                         unsigned mbar) {
    asm volatile(
        "cp.async.bulk.shared::cta.global.mbarrier::complete_tx::bytes [%0], [%1], %2, [%3];"
        :: "r"(dst), "l"(src), "r"(bytes), "r"(mbar) : "memory");
}
// acquire-poll a global ready counter until >= target
__device__ __forceinline__ void wait_cnt(const unsigned* p, unsigned target) {
    unsigned v;
    do {
        asm volatile("ld.acquire.gpu.u32 %0, [%1];" : "=r"(v) : "l"(p) : "memory");
    } while (v < target);
}

// ---------------- mask (bit-packed; atomicOr idempotent across replays) ----
__global__ void __launch_bounds__(256) mask_kernel(const float* __restrict__ x) {
    int warp = (blockIdx.x * 256 + threadIdx.x) >> 5;
    int lane = threadIdx.x & 31;
    if (warp >= NB * NT) return;
    int b = warp >> 9, t = warp & 511;
    const float4* p = (const float4*)(x + (long)warp * NF);
    float4 v1 = p[lane];
    float4 v2 = p[lane + 32];
    bool nz = v1.x != 0.f || v1.y != 0.f || v1.z != 0.f || v1.w != 0.f ||
              v2.x != 0.f || v2.y != 0.f || v2.z != 0.f || v2.w != 0.f;
    unsigned m = __ballot_sync(0xffffffffu, nz);
    if (lane == 0 && m != 0u)
        atomicOr(&g_maskw[b * 16 + (t >> 5)], 1u << (t & 31));
}

// ---------------- prep: weights (block layout, swizzled, permuted) ----------------
__global__ void __launch_bounds__(256) prep_weights(
    const float* __restrict__ W, const float* __restrict__ U, const float* __restrict__ b) {
    long idx = (long)blockIdx.x * 256 + threadIdx.x; // 10*NG*128
    int hs = (int)(idx & 127);
    int n = (int)((idx >> 7) & (NG - 1));
    int kt = (int)(idx >> 19);
    int cc = (hs >> 4) ^ (n & 7);
    int hc = (cc << 4) | (hs & 15);
    int kl = (hc & ~15) | c_perm[hc & 15];
    int k = kt * BK + kl;
    int gate = n & 3, j = n >> 2;
    float v = (k < NH) ? U[(long)k * NG + gate * NH + j]
                       : W[(long)(k - NH) * NG + gate * NH + j];
    g_MB[idx] = __float2half_rn(v);
    if (hs == 0 && kt == 0) g_bI[n] = b[gate * NH + j];
}

// ---------------- prep: x blocks + MLP combine + h0 zero + counter reset --------
__global__ void __launch_bounds__(256) prep_misc(
    const float* __restrict__ x, const float* __restrict__ W1) {
    const long N0 = (long)NT * 2 * NB * 8;  // x chunks of 16 halves
    const long N1 = (long)2048 * NH;
    const long N2 = (long)HSZ / 8;          // h0 zero in uint4 units
    long idx = (long)blockIdx.x * 256 + threadIdx.x;
    if (idx < N0) {
        int cs = (int)(idx & 7);
        int bb = (int)((idx >> 3) & 255);
        int kb = (int)((idx >> 11) & 1);
        int t = (int)(idx >> 12);
        int cc = cs ^ (bb & 7);
        const float* src = x + ((long)bb * NT + t) * NF + kb * 128 + cc * 16;
        float4 v0 = *(const float4*)(src);
        float4 v1 = *(const float4*)(src + 4);
        float4 v2 = *(const float4*)(src + 8);
        float4 v3 = *(const float4*)(src + 12);
        __half2 h[8];
        h[0] = __floats2half2_rn(v0.x, v0.y);
        h[1] = __floats2half2_rn(v2.x, v2.y);
        h[2] = __floats2half2_rn(v0.z, v0.w);
        h[3] = __floats2half2_rn(v2.z, v2.w);
        h[4] = __floats2half2_rn(v1.x, v1.y);
        h[5] = __floats2half2_rn(v3.x, v3.y);
        h[6] = __floats2half2_rn(v1.z, v1.w);
        h[7] = __floats2half2_rn(v3.z, v3.w);
        __half* dst = g_xB + ((((long)t * 2 + kb) * NB + bb) * 128 + cs * 16);
        *(uint4*)(dst) = *(uint4*)(h);
        *(uint4*)(dst + 8) = *(uint4*)(h + 4);
    } else if (idx < N0 + N1) {
        long r = idx - N0;
        int k = (int)(r >> 10), m = (int)(r & (NH - 1));
        float v = (k < NH) ? (W1[(long)k * NH + m] + W1[(long)(k + NH) * NH + m])
                           : W1[(long)(k + NH) * NH + m];
        g_MLP[r] = v;
    } else if (idx < N0 + N1 + N2) {
        ((uint4*)g_h)[idx - N0 - N1] = make_uint4(0, 0, 0, 0);
    } else if (idx < N0 + N1 + N2 + 16) {
        g_hcnt[idx - N0 - N1 - N2] = 0;   // reset ready counters each launch
    }
}

// ---------------- persistent LSTM recurrence (K-split + frag DB) -----------------
__global__ void __launch_bounds__(NTHREADS) lstm_persistent() {
    extern __shared__ __align__(128) char dsm[];
    __half* sh = (__half*)dsm;
    float* ms = (float*)(dsm + NST * ST_BY);   // partial-acc merge buffer
    __shared__ __align__(8) unsigned long long s_mbar[NST];

    const int tid = threadIdx.x;
    const int lane = tid & 31;
    const int w = tid >> 5;
    const int kw = w >> 3;      // K half: 0 -> ch 0..3, 1 -> ch 4..7
    const int wq = w & 7;       // tile position within 8
    const int wm = wq & 1;
    const int wn = wq >> 1;
    const int bn = blockIdx.x * BN;
    const int bm = blockIdx.y * BM;
    const int g = lane >> 2;
    const int c = lane & 3;
    const int c4 = 4 * c;
    const int odd = c & 1;
    const int kb_own = bn >> 9;     // the single h block this CTA writes

    const unsigned smb = smem_u32(sh);
    const unsigned mbb = smem_u32(s_mbar);

    if (tid == 0)
        for (int s = 0; s < NST; ++s) mbar_init(mbb + 8 * s, 1);
    __syncthreads();

    // fragment identities (t-independent)
    const int bgA = bm + wm * 32 + g + (odd ? 8 : 0);
    const int bgB = bgA + 16;
    int jj[4], hposA[4], hposB[4];
    float4 b4[4];
#pragma unroll
    for (int nt = 0; nt < 4; ++nt) {
        int j = (bn >> 2) + wn * 8 + nt * 2 + (c >> 1);
        jj[nt] = j;
        int q = (j & ~15) | c_pinv[j & 15];
        int kb = q >> 7, hc = q & 127;
        hposA[nt] = ((kb * NB + bgA) << 7) + (((hc >> 4) ^ (bgA & 7)) << 4) + (hc & 15);
        hposB[nt] = ((kb * NB + bgB) << 7) + (((hc >> 4) ^ (bgB & 7)) << 4) + (hc & 15);
        b4[nt] = *(const float4*)(g_bI + 4 * j);
    }
    float cst[8], hst[8];
#pragma unroll
    for (int i = 0; i < 8; ++i) { cst[i] = 0.0f; hst[i] = 0.0f; }

    int ph[NST] = {0, 0, 0};
    unsigned mw0 = 0, mw1 = 0;
    float* mp = ms + (wq * 32 + lane) * 36;   // padded: stride 36 -> conflict-free

    // per-warp chunk offsets (kw-split), hoisted out of the loops
    const int ch0 = kw * 4;

    auto bulkA_fill = [&](int kt, int s, const __half* hsrc, int t) {
        const __half* asrc = (kt < 8)
            ? (hsrc + ((long)kt * NB + bm) * BK)
            : (g_xB + (((long)t * 2 + (kt - 8)) * NB + bm) * BK);
        bulk_g2s(smb + s * ST_BY, asrc, A_BY, mbb + 8 * s);
    };
    auto bulkB_fill = [&](int kt, int s) {
        bulk_g2s(smb + s * ST_BY + A_BY, g_MB + ((long)kt * NG + bn) * BK, B_BY, mbb + 8 * s);
    };

    // t=0 prologue
    if (tid == 0) {
        mbar_expect_tx(mbb + 0, (unsigned)ST_BY);
        bulkB_fill(0, 0);
        bulkA_fill(0, 0, g_h, 0);
        mbar_expect_tx(mbb + 8, (unsigned)ST_BY);
        bulkB_fill(1, 1);
        bulkA_fill(1, 1, g_h, 0);
    }

    for (int t = 0; t < NT; ++t) {
        const int srcbuf = t & 1;
        const __half* __restrict__ hsrc = g_h + srcbuf * HSZ;
        __half* __restrict__ hdst = g_h + (srcbuf ^ 1) * HSZ;
        const unsigned target = 16u * (unsigned)((t + 1) >> 1);

        if ((t & 31) == 0) {
            mw0 = g_maskw[bgA * 16 + (t >> 5)];
            mw1 = g_maskw[bgB * 16 + (t >> 5)];
        }

        float acc[2][4][4];
#pragma unroll
        for (int i = 0; i < 2; ++i)
#pragma unroll
            for (int j = 0; j < 4; ++j)
#pragma unroll
                for (int k = 0; k < 4; ++k) acc[i][j][k] = 0.0f;

        for (int kt = 0; kt < NKT; ++kt) {
            const int s = (kt + t) % NST;
            mbar_wait(mbb + 8 * s, (unsigned)ph[s]);
            ph[s] ^= 1;
            __syncthreads();
            if (tid == 0 && kt + 2 < NKT) {
                const int s2 = (kt + 2 + t) % NST;
                mbar_expect_tx(mbb + 8 * s2, (unsigned)ST_BY);
                bulkB_fill(kt + 2, s2);
                if (kt + 2 < 8 && t > 0)
                    wait_cnt(&g_hcnt[srcbuf * 8 + kt + 2], target);
                bulkA_fill(kt + 2, s2, hsrc, t);
            }

            const __half* Ab = sh + s * ST_H;
            const __half* arow = Ab + (wm * 32 + g) * BK;
            const __half* brow = Ab + A_H + (wn * 32 + g) * BK;

            // double-buffered fragment pipeline over this warp's 4 chunks
            uint2 fA[2][4], fB[2][4];
            {
                const int o = ((ch0 ^ g) << 4) + c4;
                fA[0][0] = *(const uint2*)(arow + o);
                fA[0][1] = *(const uint2*)(arow + 1024 + o);
                fA[0][2] = *(const uint2*)(arow + 2048 + o);
                fA[0][3] = *(const uint2*)(arow + 3072 + o);
                fB[0][0] = *(const uint2*)(brow + o);
                fB[0][1] = *(const uint2*)(brow + 1024 + o);
                fB[0][2] = *(const uint2*)(brow + 2048 + o);
                fB[0][3] = *(const uint2*)(brow + 3072 + o);
            }
#pragma unroll
            for (int ch4 = 0; ch4 < 4; ++ch4) {
                const int cb = ch4 & 1;
                if (ch4 < 3) {
                    const int o = (((ch0 + ch4 + 1) ^ g) << 4) + c4;
                    uint2* a = fA[cb ^ 1];
                    uint2* b = fB[cb ^ 1];
                    a[0] = *(const uint2*)(arow + o);
                    a[1] = *(const uint2*)(arow + 1024 + o);
                    a[2] = *(const uint2*)(arow + 2048 + o);
                    a[3] = *(const uint2*)(arow + 3072 + o);
                    b[0] = *(const uint2*)(brow + o);
                    b[1] = *(const uint2*)(brow + 1024 + o);
                    b[2] = *(const uint2*)(brow + 2048 + o);
                    b[3] = *(const uint2*)(brow + 3072 + o);
                }
                const uint2* a = fA[cb];
                const uint2* b = fB[cb];
                mma16(acc[0][0], a[0].x, a[1].x, a[0].y, a[1].y, b[0].x, b[0].y);
                mma16(acc[0][1], a[0].x, a[1].x, a[0].y, a[1].y, b[1].x, b[1].y);
                mma16(acc[0][2], a[0].x, a[1].x, a[0].y, a[1].y, b[2].x, b[2].y);
                mma16(acc[0][3], a[0].x, a[1].x, a[0].y, a[1].y, b[3].x, b[3].y);
                mma16(acc[1][0], a[2].x, a[3].x, a[2].y, a[3].y, b[0].x, b[0].y);
                mma16(acc[1][1], a[2].x, a[3].x, a[2].y, a[3].y, b[1].x, b[1].y);
                mma16(acc[1][2], a[2].x, a[3].x, a[2].y, a[3].y, b[2].x, b[2].y);
                mma16(acc[1][3], a[2].x, a[3].x, a[2].y, a[3].y, b[3].x, b[3].y);
            }
        }

        // merge K halves: kw=1 parks partials, kw=0 adds and runs the epilogue
        if (kw == 1) {
#pragma unroll
            for (int mt = 0; mt < 2; ++mt)
#pragma unroll
                for (int nt = 0; nt < 4; ++nt)
                    *(float4*)(mp + (mt * 4 + nt) * 4) =
                        make_float4(acc[mt][nt][0], acc[mt][nt][1],
                                    acc[mt][nt][2], acc[mt][nt][3]);
        }
        __syncthreads();
        if (kw == 0) {
#pragma unroll
            for (int mt = 0; mt < 2; ++mt)
#pragma unroll
                for (int nt = 0; nt < 4; ++nt) {
                    float4 v = *(const float4*)(mp + (mt * 4 + nt) * 4);
                    acc[mt][nt][0] += v.x;
                    acc[mt][nt][1] += v.y;
                    acc[mt][nt][2] += v.z;
                    acc[mt][nt][3] += v.w;
                }

            const unsigned bit0 = (mw0 >> (t & 31)) & 1u;
            const unsigned bit1 = (mw1 >> (t & 31)) & 1u;
#pragma unroll
            for (int i = 0; i < 8; ++i) {
                const int mt = i >> 2, nt = i & 3;
                float v0 = acc[mt][nt][0], v1 = acc[mt][nt][1];
                float v2 = acc[mt][nt][2], v3 = acc[mt][nt][3];
                float sx = odd ? v0 : v2;
                float sy = odd ? v1 : v3;
                float gx = __shfl_xor_sync(0xffffffffu, sx, 1);
                float gy = __shfl_xor_sync(0xffffffffu, sy, 1);
                float zi, zf, zg, zo;
                if (!odd) { zi = v0; zf = v1; zg = gx; zo = gy; }
                else      { zi = gx; zf = gy; zg = v2; zo = v3; }
                float4 bb = b4[nt];
                zi += bb.x; zf += bb.y; zg += bb.z; zo += bb.w;
                float iv = sigmf(zi), fv = sigmf(zf), gv = tanhfa(zg), ov = sigmf(zo);
                float cn = fv * cst[i] + iv * gv;
                float hn = ov * tanhfa(cn);
                unsigned msk = mt ? bit1 : bit0;
                if (!msk) { cn = cst[i]; hn = hst[i]; }
                cst[i] = cn;
                hst[i] = hn;
                hdst[mt ? hposB[nt] : hposA[nt]] = __float2half_rn(hn);
            }
        }

        // publish our h block (release), then start next step's fills
        __syncthreads();
        if (tid == 0) {
            __threadfence();
            atomicAdd(&g_hcnt[(srcbuf ^ 1) * 8 + kb_own], 1u);
            if (t + 1 < NT) {
                const int sA = (t + 1) % 3, sB = (t + 2) % 3;
                mbar_expect_tx(mbb + 8 * sA, (unsigned)ST_BY);
                bulkB_fill(0, sA);
                mbar_expect_tx(mbb + 8 * sB, (unsigned)ST_BY);
                bulkB_fill(1, sB);
                const __half* hnext = g_h + (srcbuf ^ 1) * HSZ;
                const unsigned ntarget = 16u * (unsigned)((t + 2) >> 1);
                wait_cnt(&g_hcnt[(srcbuf ^ 1) * 8 + 0], ntarget);
                bulkA_fill(0, sA, hnext, t + 1);
                wait_cnt(&g_hcnt[(srcbuf ^ 1) * 8 + 1], ntarget);
                bulkA_fill(1, sB, hnext, t + 1);
            }
        }
    }

    // final c (fp32) for the MLP head
    if (kw == 0) {
#pragma unroll
        for (int i = 0; i < 8; ++i) {
            int bg = (i >> 2) ? bgB : bgA;
            g_cf[(long)bg * NH + jj[i & 3]] = cst[i];
        }
    }
    __syncthreads();
    if (tid == 0)
        for (int s = 0; s < NST; ++s) mbar_inval(mbb + 8 * s);
}

// un-permute/un-swizzle final h (buffer 0 after 512 steps) to fp32
__global__ void __launch_bounds__(256) unperm_h() {
    int idx = blockIdx.x * 256 + threadIdx.x; // NB*NH
    int b = idx >> 10, j = idx & 1023;
    int q = (j & ~15) | c_pinv[j & 15];
    int kb = q >> 7, hc = q & 127;
    long off = (((long)kb * NB + b) << 7) + (((hc >> 4) ^ (b & 7)) << 4) + (hc & 15);
    g_hf[idx] = __half2float(g_h[off]);
}

// ---------------- MLP head ----------------
__global__ void __launch_bounds__(256) mlp1_kernel(const float* __restrict__ b1) {
    __shared__ float a_s[64 * 20];
    __shared__ float b_s[16 * 68];
    int tid = threadIdx.x;
    int bn = blockIdx.x * 64, bm = blockIdx.y * 64;
    int ty = tid >> 4, tx = tid & 15;
    float acc[4][4];
#pragma unroll
    for (int i = 0; i < 4; ++i)
#pragma unroll
        for (int j = 0; j < 4; ++j) acc[i][j] = 0.0f;

    for (int kt = 0; kt < 128; ++kt) {
        int k0 = kt * 16;
        {
            int m = tid >> 2, kq = tid & 3;
            int k = k0 + 4 * kq;
            const float* src = (k < NH) ? (g_hf + (long)(bm + m) * NH + k)
                                        : (g_cf + (long)(bm + m) * NH + (k - NH));
            *(float4*)(a_s + m * 20 + 4 * kq) = *(const float4*)src;
        }
        {
            int kr = tid >> 4, cq = tid & 15;
            *(float4*)(b_s + kr * 68 + 4 * cq) =
                *(const float4*)(g_MLP + (long)(k0 + kr) * NH + bn + 4 * cq);
        }
        __syncthreads();
#pragma unroll
        for (int k = 0; k < 16; ++k) {
            float ar[4], br[4];
#pragma unroll
            for (int i = 0; i < 4; ++i) {
                ar[i] = a_s[(4 * ty + i) * 20 + k];
                br[i] = b_s[k * 68 + 4 * tx + i];
            }
#pragma unroll
            for (int i = 0; i < 4; ++i)
#pragma unroll
                for (int j = 0; j < 4; ++j) acc[i][j] += ar[i] * br[j];
        }
        __syncthreads();
    }
#pragma unroll
    for (int i = 0; i < 4; ++i)
#pragma unroll
        for (int j = 0; j < 4; ++j) {
            float v = acc[i][j] + b1[bn + 4 * tx + j];
            v = v > 0.0f ? v : 0.2f * v;
            g_y1[(long)(bm + 4 * ty + i) * NH + bn + 4 * tx + j] = v;
        }
}

__global__ void __launch_bounds__(64) mlp2_kernel(
    const float* __restrict__ W2, const float* __restrict__ b2, float* __restrict__ out) {
    __shared__ float row[NH];
    int bg = blockIdx.x;
    int o = threadIdx.x;
    for (int i = o; i < NH; i += 64) row[i] = g_y1[(long)bg * NH + i];
    __syncthreads();
    float acc = b2[o];
#pragma unroll 8
    for (int k = 0; k < NH; ++k) acc += row[k] * W2[(long)k * NOUT + o];
    out[(long)bg * NOUT + o] = acc;
}

// ---------------- launch ----------------
extern "C" void kernel_launch(void* const* d_in, const int* in_sizes, int n_in,
                              void* d_out, int out_size) {
    const float* x  = (const float*)d_in[0];
    const float* W  = (const float*)d_in[1];
    const float* U  = (const float*)d_in[2];
    const float* b  = (const float*)d_in[3];
    const float* W1 = (const float*)d_in[4];
    const float* b1 = (const float*)d_in[5];
    const float* W2 = (const float*)d_in[6];
    const float* b2 = (const float*)d_in[7];
    float* out = (float*)d_out;

    cudaFuncSetAttribute(lstm_persistent,
                         cudaFuncAttributeMaxDynamicSharedMemorySize, SMEM_BYTES);

    const long WN = (long)10 * NG * 128;
    const long MN = (long)NT * 2 * NB * 8 + (long)2048 * NH + (long)HSZ / 8 + 16;

    // lstm_persistent is the 4th launch (ncu profiles launch index 3)
    mask_kernel<<<(NB * NT * 32) / 256, 256>>>(x);
    prep_weights<<<(int)(WN / 256), 256>>>(W, U, b);
    prep_misc<<<(int)((MN + 255) / 256), 256>>>(x, W1);
    lstm_persistent<<<dim3(NG / BN, NB / BM), NTHREADS, SMEM_BYTES>>>();
    unperm_h<<<(NB * NH) / 256, 256>>>();
    mlp1_kernel<<<dim3(NH / 64, NB / 64), 256>>>(b1);
    mlp2_kernel<<<NB, 64>>>(W2, b2, out);
}

// round 14
// speedup vs baseline: 1.0527x; 1.0527x over previous
#include <cuda_runtime.h>
#include <cuda_fp16.h>
#include <cstdint>

// Problem dims
constexpr int NB = 256, NT = 512, NF = 256, NH = 1024, NG = 4096;
constexpr int NKD = NH + NF; // 1280
constexpr int NOUT = 64;

// Persistent step-GEMM tiling (fp16 mma.sync + cp.async.bulk, 4-stage, frag-DB,
// sync every 2 kt)
constexpr int BM = 64, BN = 128, BK = 128;
constexpr int NKT = NKD / BK;   // 10 (kt 0..7 = h blocks, 8..9 = x blocks)
constexpr int NST = 4;
constexpr int A_BY = BM * BK * 2;        // 16384 B
constexpr int B_BY = BN * BK * 2;        // 32768 B
constexpr int ST_BY = A_BY + B_BY;       // 49152 B
constexpr int ST_H = ST_BY / 2;
constexpr int A_H = A_BY / 2;
constexpr int SMEM_BYTES = NST * ST_BY;  // 196608
constexpr int NCTAS = (NB / BM) * (NG / BN); // 128
constexpr int HSZ = 8 * NB * BK;         // halves per h buffer

// per-16 k permutation: position q holds k = PERM[q]
__device__ __constant__ int c_perm[16] = {0,1,8,9, 2,3,10,11, 4,5,12,13, 6,7,14,15};
__device__ __constant__ int c_pinv[16] = {0,1,4,5, 8,9,12,13, 2,3,6,7, 10,11,14,15};

// ---------------- device scratch ----------------
__device__ __half g_MB[(long)10 * NG * BK];      // [kt(10)][n][128] weights
__device__ __half g_xB[(long)NT * 2 * NB * BK];  // [t][kb][b][128] fp16 x blocks
__device__ __half g_h[2 * HSZ];                  // ping-pong hidden, block layout
__device__ float  g_bI[NG];
__device__ float  g_MLP[2048 * NH];
__device__ float  g_cf[NB * NH];
__device__ float  g_hf[NB * NH];
__device__ float  g_y1[NB * NH];
__device__ unsigned g_maskw[NB * 16];
__device__ unsigned g_hcnt[16];                  // [buf][kb] h-block ready counters

// ---------------- helpers ----------------
__device__ __forceinline__ unsigned smem_u32(const void* p) {
    unsigned a;
    asm("{ .reg .u64 t; cvta.to.shared.u64 t, %1; cvt.u32.u64 %0, t; }" : "=r"(a) : "l"(p));
    return a;
}
__device__ __forceinline__ float fex2(float x) {
    float y; asm("ex2.approx.f32 %0, %1;" : "=f"(y) : "f"(x)); return y;
}
__device__ __forceinline__ float frcp(float x) {
    float y; asm("rcp.approx.f32 %0, %1;" : "=f"(y) : "f"(x)); return y;
}
__device__ __forceinline__ float sigmf(float x) {
    return frcp(1.0f + fex2(-1.4426950408889634f * x));
}
__device__ __forceinline__ float tanhfa(float x) {
    return 1.0f - 2.0f * frcp(1.0f + fex2(2.8853900817779268f * x));
}
__device__ __forceinline__ void mma16(float* d, unsigned a0, unsigned a1, unsigned a2,
                                      unsigned a3, unsigned b0, unsigned b1) {
    asm volatile(
        "mma.sync.aligned.m16n8k16.row.col.f32.f16.f16.f32 "
        "{%0,%1,%2,%3}, {%4,%5,%6,%7}, {%8,%9}, {%0,%1,%2,%3};"
        : "+f"(d[0]), "+f"(d[1]), "+f"(d[2]), "+f"(d[3])
        : "r"(a0), "r"(a1), "r"(a2), "r"(a3), "r"(b0), "r"(b1));
}
__device__ __forceinline__ void mbar_init(unsigned mbar, unsigned cnt) {
    asm volatile("mbarrier.init.shared.b64 [%0], %1;" :: "r"(mbar), "r"(cnt) : "memory");
}
__device__ __forceinline__ void mbar_inval(unsigned mbar) {
    asm volatile("mbarrier.inval.shared.b64 [%0];" :: "r"(mbar) : "memory");
}
__device__ __forceinline__ void mbar_expect_tx(unsigned mbar, unsigned bytes) {
    asm volatile("mbarrier.arrive.expect_tx.shared.b64 _, [%0], %1;"
                 :: "r"(mbar), "r"(bytes) : "memory");
}
__device__ __forceinline__ void mbar_wait(unsigned mbar, unsigned parity) {
    asm volatile(
        "{\n\t.reg .pred P;\n"
        "W%=:\n\t"
        "mbarrier.try_wait.parity.acquire.cta.shared::cta.b64 P, [%0], %1, 0x989680;\n\t"
        "@!P bra W%=;\n\t}"
        :: "r"(mbar), "r"(parity) : "memory");
}
__device__ __forceinline__ void bulk_g2s(unsigned dst, const void* src, unsigned bytes,
                                         unsigned mbar) {
    asm volatile(
        "cp.async.bulk.shared::cta.global.mbarrier::complete_tx::bytes [%0], [%1], %2, [%3];"
        :: "r"(dst), "l"(src), "r"(bytes), "r"(mbar) : "memory");
}
// acquire-poll a global ready counter until >= target
__device__ __forceinline__ void wait_cnt(const unsigned* p, unsigned target) {
    unsigned v;
    do {
        asm volatile("ld.acquire.gpu.u32 %0, [%1];" : "=r"(v) : "l"(p) : "memory");
    } while (v < target);
}

// ---------------- mask (bit-packed; atomicOr idempotent across replays) ----
__global__ void __launch_bounds__(256) mask_kernel(const float* __restrict__ x) {
    int warp = (blockIdx.x * 256 + threadIdx.x) >> 5;
    int lane = threadIdx.x & 31;
    if (warp >= NB * NT) return;
    int b = warp >> 9, t = warp & 511;
    const float4* p = (const float4*)(x + (long)warp * NF);
    float4 v1 = p[lane];
    float4 v2 = p[lane + 32];
    bool nz = v1.x != 0.f || v1.y != 0.f || v1.z != 0.f || v1.w != 0.f ||
              v2.x != 0.f || v2.y != 0.f || v2.z != 0.f || v2.w != 0.f;
    unsigned m = __ballot_sync(0xffffffffu, nz);
    if (lane == 0 && m != 0u)
        atomicOr(&g_maskw[b * 16 + (t >> 5)], 1u << (t & 31));
}

// ---------------- prep: weights (block layout, swizzled, permuted) ----------------
__global__ void __launch_bounds__(256) prep_weights(
    const float* __restrict__ W, const float* __restrict__ U, const float* __restrict__ b) {
    long idx = (long)blockIdx.x * 256 + threadIdx.x; // 10*NG*128
    int hs = (int)(idx & 127);
    int n = (int)((idx >> 7) & (NG - 1));
    int kt = (int)(idx >> 19);
    int cc = (hs >> 4) ^ (n & 7);
    int hc = (cc << 4) | (hs & 15);
    int kl = (hc & ~15) | c_perm[hc & 15];
    int k = kt * BK + kl;
    int gate = n & 3, j = n >> 2;
    float v = (k < NH) ? U[(long)k * NG + gate * NH + j]
                       : W[(long)(k - NH) * NG + gate * NH + j];
    g_MB[idx] = __float2half_rn(v);
    if (hs == 0 && kt == 0) g_bI[n] = b[gate * NH + j];
}

// ---------------- prep: x blocks + MLP combine + h0 zero + counter reset --------
__global__ void __launch_bounds__(256) prep_misc(
    const float* __restrict__ x, const float* __restrict__ W1) {
    const long N0 = (long)NT * 2 * NB * 8;  // x chunks of 16 halves
    const long N1 = (long)2048 * NH;
    const long N2 = (long)HSZ / 8;          // h0 zero in uint4 units
    long idx = (long)blockIdx.x * 256 + threadIdx.x;
    if (idx < N0) {
        int cs = (int)(idx & 7);
        int bb = (int)((idx >> 3) & 255);
        int kb = (int)((idx >> 11) & 1);
        int t = (int)(idx >> 12);
        int cc = cs ^ (bb & 7);
        const float* src = x + ((long)bb * NT + t) * NF + kb * 128 + cc * 16;
        float4 v0 = *(const float4*)(src);
        float4 v1 = *(const float4*)(src + 4);
        float4 v2 = *(const float4*)(src + 8);
        float4 v3 = *(const float4*)(src + 12);
        __half2 h[8];
        h[0] = __floats2half2_rn(v0.x, v0.y);
        h[1] = __floats2half2_rn(v2.x, v2.y);
        h[2] = __floats2half2_rn(v0.z, v0.w);
        h[3] = __floats2half2_rn(v2.z, v2.w);
        h[4] = __floats2half2_rn(v1.x, v1.y);
        h[5] = __floats2half2_rn(v3.x, v3.y);
        h[6] = __floats2half2_rn(v1.z, v1.w);
        h[7] = __floats2half2_rn(v3.z, v3.w);
        __half* dst = g_xB + ((((long)t * 2 + kb) * NB + bb) * 128 + cs * 16);
        *(uint4*)(dst) = *(uint4*)(h);
        *(uint4*)(dst + 8) = *(uint4*)(h + 4);
    } else if (idx < N0 + N1) {
        long r = idx - N0;
        int k = (int)(r >> 10), m = (int)(r & (NH - 1));
        float v = (k < NH) ? (W1[(long)k * NH + m] + W1[(long)(k + NH) * NH + m])
                           : W1[(long)(k + NH) * NH + m];
        g_MLP[r] = v;
    } else if (idx < N0 + N1 + N2) {
        ((uint4*)g_h)[idx - N0 - N1] = make_uint4(0, 0, 0, 0);
    } else if (idx < N0 + N1 + N2 + 16) {
        g_hcnt[idx - N0 - N1 - N2] = 0;   // reset ready counters each launch
    }
}

// ---------------- persistent LSTM recurrence (4-stage, frag DB, half-syncs) ------
__global__ void __launch_bounds__(256) lstm_persistent() {
    extern __shared__ __align__(128) char dsm[];
    __half* sh = (__half*)dsm;
    __shared__ __align__(8) unsigned long long s_mbar[NST];

    const int tid = threadIdx.x;
    const int lane = tid & 31;
    const int w = tid >> 5;
    const int wm = w & 1;
    const int wn = w >> 1;
    const int bn = blockIdx.x * BN;
    const int bm = blockIdx.y * BM;
    const int g = lane >> 2;
    const int c = lane & 3;
    const int c4 = 4 * c;
    const int odd = c & 1;
    const int kb_own = bn >> 9;     // the single h block this CTA writes

    const unsigned smb = smem_u32(sh);
    const unsigned mbb = smem_u32(s_mbar);

    if (tid == 0)
        for (int s = 0; s < NST; ++s) mbar_init(mbb + 8 * s, 1);
    __syncthreads();

    // fragment identities (t-independent)
    const int bgA = bm + wm * 32 + g + (odd ? 8 : 0);
    const int bgB = bgA + 16;
    int jj[4], hposA[4], hposB[4];
    float4 b4[4];
#pragma unroll
    for (int nt = 0; nt < 4; ++nt) {
        int j = (bn >> 2) + wn * 8 + nt * 2 + (c >> 1);
        jj[nt] = j;
        int q = (j & ~15) | c_pinv[j & 15];
        int kb = q >> 7, hc = q & 127;
        hposA[nt] = ((kb * NB + bgA) << 7) + (((hc >> 4) ^ (bgA & 7)) << 4) + (hc & 15);
        hposB[nt] = ((kb * NB + bgB) << 7) + (((hc >> 4) ^ (bgB & 7)) << 4) + (hc & 15);
        b4[nt] = *(const float4*)(g_bI + 4 * j);
    }
    float cst[8], hst[8];
#pragma unroll
    for (int i = 0; i < 8; ++i) { cst[i] = 0.0f; hst[i] = 0.0f; }

    int ph[NST] = {0, 0, 0, 0};
    unsigned mw0 = 0, mw1 = 0;

    auto bulkA_fill = [&](int kt, int s, const __half* hsrc, int t) {
        const __half* asrc = (kt < 8)
            ? (hsrc + ((long)kt * NB + bm) * BK)
            : (g_xB + (((long)t * 2 + (kt - 8)) * NB + bm) * BK);
        bulk_g2s(smb + s * ST_BY, asrc, A_BY, mbb + 8 * s);
    };
    auto bulkB_fill = [&](int kt, int s) {
        bulk_g2s(smb + s * ST_BY + A_BY, g_MB + ((long)kt * NG + bn) * BK, B_BY, mbb + 8 * s);
    };
    // full fill with h-block gating (A after B so B streams while polling)
    auto fill_full = [&](int kt, int t, const __half* hsrc, int srcbuf, unsigned target) {
        const int s = (2 * t + kt) & 3;
        mbar_expect_tx(mbb + 8 * s, (unsigned)ST_BY);
        bulkB_fill(kt, s);
        if (kt < 8 && t > 0) wait_cnt(&g_hcnt[srcbuf * 8 + kt], target);
        bulkA_fill(kt, s, hsrc, t);
    };

    // t=0 prologue: full fills kt0 (stage 0), kt1 (stage 1), kt2 (stage 2)
    if (tid == 0) {
        for (int kt = 0; kt < 3; ++kt) {
            mbar_expect_tx(mbb + 8 * kt, (unsigned)ST_BY);
            bulkB_fill(kt, kt);
            bulkA_fill(kt, kt, g_h, 0);
        }
    }

    for (int t = 0; t < NT; ++t) {
        const int srcbuf = t & 1;
        const __half* __restrict__ hsrc = g_h + srcbuf * HSZ;
        __half* __restrict__ hdst = g_h + (srcbuf ^ 1) * HSZ;
        const unsigned target = 16u * (unsigned)((t + 1) >> 1);
        const int t2 = 2 * t;

        if ((t & 31) == 0) {
            mw0 = g_maskw[bgA * 16 + (t >> 5)];
            mw1 = g_maskw[bgB * 16 + (t >> 5)];
        }

        float acc[2][4][4];
#pragma unroll
        for (int i = 0; i < 2; ++i)
#pragma unroll
            for (int j = 0; j < 4; ++j)
#pragma unroll
                for (int k = 0; k < 4; ++k) acc[i][j][k] = 0.0f;

        for (int kt = 0; kt < NKT; ++kt) {
            const int s = (t2 + kt) & 3;
            if ((kt & 1) == 0) {
                // even kt: one warp waits, CTA-wide sync, fills (stage-reuse safe:
                // sync proves all warps past kt-1; fills target stages of kt-2, kt-1)
                if (w == 0) mbar_wait(mbb + 8 * s, (unsigned)ph[s]);
                __syncthreads();
                if (tid == 0) {
                    if (kt == 0) {
                        fill_full(3, t, hsrc, srcbuf, target);
                    } else if (kt <= 6) {
                        fill_full(kt + 2, t, hsrc, srcbuf, target);
                        fill_full(kt + 3, t, hsrc, srcbuf, target);
                    } else if (t + 1 < NT) {  // kt == 8: next-step weight fills
                        const int sA = (t2 + 2) & 3, sB = (t2 + 3) & 3;
                        mbar_expect_tx(mbb + 8 * sA, (unsigned)ST_BY);
                        bulkB_fill(0, sA);
                        mbar_expect_tx(mbb + 8 * sB, (unsigned)ST_BY);
                        bulkB_fill(1, sB);
                    }
                }
            } else {
                mbar_wait(mbb + 8 * s, (unsigned)ph[s]);  // odd kt: per-thread wait only
            }
            ph[s] ^= 1;

            const __half* Ab = sh + s * ST_H;
            const __half* arow = Ab + (wm * 32 + g) * BK;
            const __half* brow = Ab + A_H + (wn * 32 + g) * BK;

            // double-buffered fragment pipeline over the 8 chunks
            uint2 fA[2][4], fB[2][4];
            {
                const int o = (g << 4) + c4;  // ch 0: (0^g)<<4 + c4
                fA[0][0] = *(const uint2*)(arow + o);
                fA[0][1] = *(const uint2*)(arow + 1024 + o);
                fA[0][2] = *(const uint2*)(arow + 2048 + o);
                fA[0][3] = *(const uint2*)(arow + 3072 + o);
                fB[0][0] = *(const uint2*)(brow + o);
                fB[0][1] = *(const uint2*)(brow + 1024 + o);
                fB[0][2] = *(const uint2*)(brow + 2048 + o);
                fB[0][3] = *(const uint2*)(brow + 3072 + o);
            }
#pragma unroll
            for (int ch = 0; ch < 8; ++ch) {
                const int cb = ch & 1;
                if (ch < 7) {
                    const int o = (((ch + 1) ^ g) << 4) + c4;
                    uint2* a = fA[cb ^ 1];
                    uint2* b = fB[cb ^ 1];
                    a[0] = *(const uint2*)(arow + o);
                    a[1] = *(const uint2*)(arow + 1024 + o);
                    a[2] = *(const uint2*)(arow + 2048 + o);
                    a[3] = *(const uint2*)(arow + 3072 + o);
                    b[0] = *(const uint2*)(brow + o);
                    b[1] = *(const uint2*)(brow + 1024 + o);
                    b[2] = *(const uint2*)(brow + 2048 + o);
                    b[3] = *(const uint2*)(brow + 3072 + o);
                }
                const uint2* a = fA[cb];
                const uint2* b = fB[cb];
                mma16(acc[0][0], a[0].x, a[1].x, a[0].y, a[1].y, b[0].x, b[0].y);
                mma16(acc[0][1], a[0].x, a[1].x, a[0].y, a[1].y, b[1].x, b[1].y);
                mma16(acc[0][2], a[0].x, a[1].x, a[0].y, a[1].y, b[2].x, b[2].y);
                mma16(acc[0][3], a[0].x, a[1].x, a[0].y, a[1].y, b[3].x, b[3].y);
                mma16(acc[1][0], a[2].x, a[3].x, a[2].y, a[3].y, b[0].x, b[0].y);
                mma16(acc[1][1], a[2].x, a[3].x, a[2].y, a[3].y, b[1].x, b[1].y);
                mma16(acc[1][2], a[2].x, a[3].x, a[2].y, a[3].y, b[2].x, b[2].y);
                mma16(acc[1][3], a[2].x, a[3].x, a[2].y, a[3].y, b[3].x, b[3].y);
            }
        }

        // register-state epilogue (shuffle gate quads)
        const unsigned bit0 = (mw0 >> (t & 31)) & 1u;
        const unsigned bit1 = (mw1 >> (t & 31)) & 1u;
#pragma unroll
        for (int i = 0; i < 8; ++i) {
            const int mt = i >> 2, nt = i & 3;
            float v0 = acc[mt][nt][0], v1 = acc[mt][nt][1];
            float v2 = acc[mt][nt][2], v3 = acc[mt][nt][3];
            float sx = odd ? v0 : v2;
            float sy = odd ? v1 : v3;
            float gx = __shfl_xor_sync(0xffffffffu, sx, 1);
            float gy = __shfl_xor_sync(0xffffffffu, sy, 1);
            float zi, zf, zg, zo;
            if (!odd) { zi = v0; zf = v1; zg = gx; zo = gy; }
            else      { zi = gx; zf = gy; zg = v2; zo = v3; }
            float4 bb = b4[nt];
            zi += bb.x; zf += bb.y; zg += bb.z; zo += bb.w;
            float iv = sigmf(zi), fv = sigmf(zf), gv = tanhfa(zg), ov = sigmf(zo);
            float cn = fv * cst[i] + iv * gv;
            float hn = ov * tanhfa(cn);
            unsigned msk = mt ? bit1 : bit0;
            if (!msk) { cn = cst[i]; hn = hst[i]; }
            cst[i] = cn;
            hst[i] = hn;
            hdst[mt ? hposB[nt] : hposA[nt]] = __float2half_rn(hn);
        }

        // publish our h block (release); A fills for kt0'/kt1' (B already in flight)
        // + full fill for kt2'
        __syncthreads();  // all warps past kt9 -> stage (t2)&3 reusable for kt2'
        if (tid == 0) {
            __threadfence();
            atomicAdd(&g_hcnt[(srcbuf ^ 1) * 8 + kb_own], 1u);
            if (t + 1 < NT) {
                const __half* hnext = g_h + (srcbuf ^ 1) * HSZ;
                const unsigned ntarget = 16u * (unsigned)((t + 2) >> 1);
                wait_cnt(&g_hcnt[(srcbuf ^ 1) * 8 + 0], ntarget);
                bulkA_fill(0, (t2 + 2) & 3, hnext, t + 1);
                wait_cnt(&g_hcnt[(srcbuf ^ 1) * 8 + 1], ntarget);
                bulkA_fill(1, (t2 + 3) & 3, hnext, t + 1);
                const int s2 = (t2 + 4) & 3;
                mbar_expect_tx(mbb + 8 * s2, (unsigned)ST_BY);
                bulkB_fill(2, s2);
                wait_cnt(&g_hcnt[(srcbuf ^ 1) * 8 + 2], ntarget);
                bulkA_fill(2, s2, hnext, t + 1);
            }
        }
    }

    // final c (fp32) for the MLP head
#pragma unroll
    for (int i = 0; i < 8; ++i) {
        int bg = (i >> 2) ? bgB : bgA;
        g_cf[(long)bg * NH + jj[i & 3]] = cst[i];
    }
    __syncthreads();
    if (tid == 0)
        for (int s = 0; s < NST; ++s) mbar_inval(mbb + 8 * s);
}

// un-permute/un-swizzle final h (buffer 0 after 512 steps) to fp32
__global__ void __launch_bounds__(256) unperm_h() {
    int idx = blockIdx.x * 256 + threadIdx.x; // NB*NH
    int b = idx >> 10, j = idx & 1023;
    int q = (j & ~15) | c_pinv[j & 15];
    int kb = q >> 7, hc = q & 127;
    long off = (((long)kb * NB + b) << 7) + (((hc >> 4) ^ (b & 7)) << 4) + (hc & 15);
    g_hf[idx] = __half2float(g_h[off]);
}

// ---------------- MLP head ----------------
__global__ void __launch_bounds__(256) mlp1_kernel(const float* __restrict__ b1) {
    __shared__ float a_s[64 * 20];
    __shared__ float b_s[16 * 68];
    int tid = threadIdx.x;
    int bn = blockIdx.x * 64, bm = blockIdx.y * 64;
    int ty = tid >> 4, tx = tid & 15;
    float acc[4][4];
#pragma unroll
    for (int i = 0; i < 4; ++i)
#pragma unroll
        for (int j = 0; j < 4; ++j) acc[i][j] = 0.0f;

    for (int kt = 0; kt < 128; ++kt) {
        int k0 = kt * 16;
        {
            int m = tid >> 2, kq = tid & 3;
            int k = k0 + 4 * kq;
            const float* src = (k < NH) ? (g_hf + (long)(bm + m) * NH + k)
                                        : (g_cf + (long)(bm + m) * NH + (k - NH));
            *(float4*)(a_s + m * 20 + 4 * kq) = *(const float4*)src;
        }
        {
            int kr = tid >> 4, cq = tid & 15;
            *(float4*)(b_s + kr * 68 + 4 * cq) =
                *(const float4*)(g_MLP + (long)(k0 + kr) * NH + bn + 4 * cq);
        }
        __syncthreads();
#pragma unroll
        for (int k = 0; k < 16; ++k) {
            float ar[4], br[4];
#pragma unroll
            for (int i = 0; i < 4; ++i) {
                ar[i] = a_s[(4 * ty + i) * 20 + k];
                br[i] = b_s[k * 68 + 4 * tx + i];
            }
#pragma unroll
            for (int i = 0; i < 4; ++i)
#pragma unroll
                for (int j = 0; j < 4; ++j) acc[i][j] += ar[i] * br[j];
        }
        __syncthreads();
    }
#pragma unroll
    for (int i = 0; i < 4; ++i)
#pragma unroll
        for (int j = 0; j < 4; ++j) {
            float v = acc[i][j] + b1[bn + 4 * tx + j];
            v = v > 0.0f ? v : 0.2f * v;
            g_y1[(long)(bm + 4 * ty + i) * NH + bn + 4 * tx + j] = v;
        }
}

__global__ void __launch_bounds__(64) mlp2_kernel(
    const float* __restrict__ W2, const float* __restrict__ b2, float* __restrict__ out) {
    __shared__ float row[NH];
    int bg = blockIdx.x;
    int o = threadIdx.x;
    for (int i = o; i < NH; i += 64) row[i] = g_y1[(long)bg * NH + i];
    __syncthreads();
    float acc = b2[o];
#pragma unroll 8
    for (int k = 0; k < NH; ++k) acc += row[k] * W2[(long)k * NOUT + o];
    out[(long)bg * NOUT + o] = acc;
}

// ---------------- launch ----------------
extern "C" void kernel_launch(void* const* d_in, const int* in_sizes, int n_in,
                              void* d_out, int out_size) {
    const float* x  = (const float*)d_in[0];
    const float* W  = (const float*)d_in[1];
    const float* U  = (const float*)d_in[2];
    const float* b  = (const float*)d_in[3];
    const float* W1 = (const float*)d_in[4];
    const float* b1 = (const float*)d_in[5];
    const float* W2 = (const float*)d_in[6];
    const float* b2 = (const float*)d_in[7];
    float* out = (float*)d_out;

    cudaFuncSetAttribute(lstm_persistent,
                         cudaFuncAttributeMaxDynamicSharedMemorySize, SMEM_BYTES);

    const long WN = (long)10 * NG * 128;
    const long MN = (long)NT * 2 * NB * 8 + (long)2048 * NH + (long)HSZ / 8 + 16;

    // lstm_persistent is the 4th launch (ncu profiles launch index 3)
    mask_kernel<<<(NB * NT * 32) / 256, 256>>>(x);
    prep_weights<<<(int)(WN / 256), 256>>>(W, U, b);
    prep_misc<<<(int)((MN + 255) / 256), 256>>>(x, W1);
    lstm_persistent<<<dim3(NG / BN, NB / BM), 256, SMEM_BYTES>>>();
    unperm_h<<<(NB * NH) / 256, 256>>>();
    mlp1_kernel<<<dim3(NH / 64, NB / 64), 256>>>(b1);
    mlp2_kernel<<<NB, 64>>>(W2, b2, out);
}

// round 15
// speedup vs baseline: 1.1030x; 1.0478x over previous
#include <cuda_runtime.h>
#include <cuda_fp16.h>
#include <cstdint>

// Problem dims
constexpr int NB = 256, NT = 512, NF = 256, NH = 1024, NG = 4096;
constexpr int NKD = NH + NF; // 1280
constexpr int NOUT = 64;

// Persistent step-GEMM tiling (fp16 mma.sync + cp.async.bulk, 4-stage, frag-DB,
// sync every 2 steps of the pipeline, x-blocks processed FIRST each step)
constexpr int BM = 64, BN = 128, BK = 128;
constexpr int NKT = NKD / BK;   // 10
constexpr int NST = 4;
constexpr int A_BY = BM * BK * 2;        // 16384 B
constexpr int B_BY = BN * BK * 2;        // 32768 B
constexpr int ST_BY = A_BY + B_BY;       // 49152 B
constexpr int ST_H = ST_BY / 2;
constexpr int A_H = A_BY / 2;
constexpr int SMEM_BYTES = NST * ST_BY;  // 196608
constexpr int NCTAS = (NB / BM) * (NG / BN); // 128
constexpr int HSZ = 8 * NB * BK;         // halves per h buffer

// per-16 k permutation: position q holds k = PERM[q]
__device__ __constant__ int c_perm[16] = {0,1,8,9, 2,3,10,11, 4,5,12,13, 6,7,14,15};
__device__ __constant__ int c_pinv[16] = {0,1,4,5, 8,9,12,13, 2,3,6,7, 10,11,14,15};

// ---------------- device scratch ----------------
__device__ __half g_MB[(long)10 * NG * BK];      // [kt(10)][n][128] weights
__device__ __half g_xB[(long)NT * 2 * NB * BK];  // [t][kb][b][128] fp16 x blocks
__device__ __half g_h[2 * HSZ];                  // ping-pong hidden, block layout
__device__ float  g_bI[NG];
__device__ float  g_MLP[2048 * NH];
__device__ float  g_cf[NB * NH];
__device__ float  g_hf[NB * NH];
__device__ float  g_y1[NB * NH];
__device__ unsigned g_maskw[NB * 16];
__device__ unsigned g_hcnt[16];                  // [buf][kb] h-block ready counters

// ---------------- helpers ----------------
__device__ __forceinline__ unsigned smem_u32(const void* p) {
    unsigned a;
    asm("{ .reg .u64 t; cvta.to.shared.u64 t, %1; cvt.u32.u64 %0, t; }" : "=r"(a) : "l"(p));
    return a;
}
__device__ __forceinline__ float fex2(float x) {
    float y; asm("ex2.approx.f32 %0, %1;" : "=f"(y) : "f"(x)); return y;
}
__device__ __forceinline__ float frcp(float x) {
    float y; asm("rcp.approx.f32 %0, %1;" : "=f"(y) : "f"(x)); return y;
}
__device__ __forceinline__ float sigmf(float x) {
    return frcp(1.0f + fex2(-1.4426950408889634f * x));
}
__device__ __forceinline__ float tanhfa(float x) {
    return 1.0f - 2.0f * frcp(1.0f + fex2(2.8853900817779268f * x));
}
__device__ __forceinline__ void mma16(float* d, unsigned a0, unsigned a1, unsigned a2,
                                      unsigned a3, unsigned b0, unsigned b1) {
    asm volatile(
        "mma.sync.aligned.m16n8k16.row.col.f32.f16.f16.f32 "
        "{%0,%1,%2,%3}, {%4,%5,%6,%7}, {%8,%9}, {%0,%1,%2,%3};"
        : "+f"(d[0]), "+f"(d[1]), "+f"(d[2]), "+f"(d[3])
        : "r"(a0), "r"(a1), "r"(a2), "r"(a3), "r"(b0), "r"(b1));
}
__device__ __forceinline__ void mbar_init(unsigned mbar, unsigned cnt) {
    asm volatile("mbarrier.init.shared.b64 [%0], %1;" :: "r"(mbar), "r"(cnt) : "memory");
}
__device__ __forceinline__ void mbar_inval(unsigned mbar) {
    asm volatile("mbarrier.inval.shared.b64 [%0];" :: "r"(mbar) : "memory");
}
__device__ __forceinline__ void mbar_expect_tx(unsigned mbar, unsigned bytes) {
    asm volatile("mbarrier.arrive.expect_tx.shared.b64 _, [%0], %1;"
                 :: "r"(mbar), "r"(bytes) : "memory");
}
__device__ __forceinline__ void mbar_wait(unsigned mbar, unsigned parity) {
    asm volatile(
        "{\n\t.reg .pred P;\n"
        "W%=:\n\t"
        "mbarrier.try_wait.parity.acquire.cta.shared::cta.b64 P, [%0], %1, 0x989680;\n\t"
        "@!P bra W%=;\n\t}"
        :: "r"(mbar), "r"(parity) : "memory");
}
__device__ __forceinline__ void bulk_g2s(unsigned dst, const void* src, unsigned bytes,
                                         unsigned mbar) {
    asm volatile(
        "cp.async.bulk.shared::cta.global.mbarrier::complete_tx::bytes [%0], [%1], %2, [%3];"
        :: "r"(dst), "l"(src), "r"(bytes), "r"(mbar) : "memory");
}
// acquire-poll a global ready counter until >= target
__device__ __forceinline__ void wait_cnt(const unsigned* p, unsigned target) {
    unsigned v;
    do {
        asm volatile("ld.acquire.gpu.u32 %0, [%1];" : "=r"(v) : "l"(p) : "memory");
    } while (v < target);
}

// ---------------- mask (bit-packed; atomicOr idempotent across replays) ----
__global__ void __launch_bounds__(256) mask_kernel(const float* __restrict__ x) {
    int warp = (blockIdx.x * 256 + threadIdx.x) >> 5;
    int lane = threadIdx.x & 31;
    if (warp >= NB * NT) return;
    int b = warp >> 9, t = warp & 511;
    const float4* p = (const float4*)(x + (long)warp * NF);
    float4 v1 = p[lane];
    float4 v2 = p[lane + 32];
    bool nz = v1.x != 0.f || v1.y != 0.f || v1.z != 0.f || v1.w != 0.f ||
              v2.x != 0.f || v2.y != 0.f || v2.z != 0.f || v2.w != 0.f;
    unsigned m = __ballot_sync(0xffffffffu, nz);
    if (lane == 0 && m != 0u)
        atomicOr(&g_maskw[b * 16 + (t >> 5)], 1u << (t & 31));
}

// ---------------- prep: weights (block layout, swizzled, permuted) ----------------
__global__ void __launch_bounds__(256) prep_weights(
    const float* __restrict__ W, const float* __restrict__ U, const float* __restrict__ b) {
    long idx = (long)blockIdx.x * 256 + threadIdx.x; // 10*NG*128
    int hs = (int)(idx & 127);
    int n = (int)((idx >> 7) & (NG - 1));
    int kt = (int)(idx >> 19);
    int cc = (hs >> 4) ^ (n & 7);
    int hc = (cc << 4) | (hs & 15);
    int kl = (hc & ~15) | c_perm[hc & 15];
    int k = kt * BK + kl;
    int gate = n & 3, j = n >> 2;
    float v = (k < NH) ? U[(long)k * NG + gate * NH + j]
                       : W[(long)(k - NH) * NG + gate * NH + j];
    g_MB[idx] = __float2half_rn(v);
    if (hs == 0 && kt == 0) g_bI[n] = b[gate * NH + j];
}

// ---------------- prep: x blocks + MLP combine + h0 zero + counter reset --------
__global__ void __launch_bounds__(256) prep_misc(
    const float* __restrict__ x, const float* __restrict__ W1) {
    const long N0 = (long)NT * 2 * NB * 8;  // x chunks of 16 halves
    const long N1 = (long)2048 * NH;
    const long N2 = (long)HSZ / 8;          // h0 zero in uint4 units
    long idx = (long)blockIdx.x * 256 + threadIdx.x;
    if (idx < N0) {
        int cs = (int)(idx & 7);
        int bb = (int)((idx >> 3) & 255);
        int kb = (int)((idx >> 11) & 1);
        int t = (int)(idx >> 12);
        int cc = cs ^ (bb & 7);
        const float* src = x + ((long)bb * NT + t) * NF + kb * 128 + cc * 16;
        float4 v0 = *(const float4*)(src);
        float4 v1 = *(const float4*)(src + 4);
        float4 v2 = *(const float4*)(src + 8);
        float4 v3 = *(const float4*)(src + 12);
        __half2 h[8];
        h[0] = __floats2half2_rn(v0.x, v0.y);
        h[1] = __floats2half2_rn(v2.x, v2.y);
        h[2] = __floats2half2_rn(v0.z, v0.w);
        h[3] = __floats2half2_rn(v2.z, v2.w);
        h[4] = __floats2half2_rn(v1.x, v1.y);
        h[5] = __floats2half2_rn(v3.x, v3.y);
        h[6] = __floats2half2_rn(v1.z, v1.w);
        h[7] = __floats2half2_rn(v3.z, v3.w);
        __half* dst = g_xB + ((((long)t * 2 + kb) * NB + bb) * 128 + cs * 16);
        *(uint4*)(dst) = *(uint4*)(h);
        *(uint4*)(dst + 8) = *(uint4*)(h + 4);
    } else if (idx < N0 + N1) {
        long r = idx - N0;
        int k = (int)(r >> 10), m = (int)(r & (NH - 1));
        float v = (k < NH) ? (W1[(long)k * NH + m] + W1[(long)(k + NH) * NH + m])
                           : W1[(long)(k + NH) * NH + m];
        g_MLP[r] = v;
    } else if (idx < N0 + N1 + N2) {
        ((uint4*)g_h)[idx - N0 - N1] = make_uint4(0, 0, 0, 0);
    } else if (idx < N0 + N1 + N2 + 16) {
        g_hcnt[idx - N0 - N1 - N2] = 0;   // reset ready counters each launch
    }
}

// ---------------- persistent LSTM recurrence (x-first, 4-stage, half-syncs) ------
__global__ void __launch_bounds__(256) lstm_persistent() {
    extern __shared__ __align__(128) char dsm[];
    __half* sh = (__half*)dsm;
    __shared__ __align__(8) unsigned long long s_mbar[NST];

    const int tid = threadIdx.x;
    const int lane = tid & 31;
    const int w = tid >> 5;
    const int wm = w & 1;
    const int wn = w >> 1;
    const int bn = blockIdx.x * BN;
    const int bm = blockIdx.y * BM;
    const int g = lane >> 2;
    const int c = lane & 3;
    const int c4 = 4 * c;
    const int odd = c & 1;
    const int kb_own = bn >> 9;     // the single h block this CTA writes

    const unsigned smb = smem_u32(sh);
    const unsigned mbb = smem_u32(s_mbar);

    if (tid == 0)
        for (int s = 0; s < NST; ++s) mbar_init(mbb + 8 * s, 1);
    __syncthreads();

    // fragment identities (t-independent)
    const int bgA = bm + wm * 32 + g + (odd ? 8 : 0);
    const int bgB = bgA + 16;
    int jj[4], hposA[4], hposB[4];
    float4 b4[4];
#pragma unroll
    for (int nt = 0; nt < 4; ++nt) {
        int j = (bn >> 2) + wn * 8 + nt * 2 + (c >> 1);
        jj[nt] = j;
        int q = (j & ~15) | c_pinv[j & 15];
        int kb = q >> 7, hc = q & 127;
        hposA[nt] = ((kb * NB + bgA) << 7) + (((hc >> 4) ^ (bgA & 7)) << 4) + (hc & 15);
        hposB[nt] = ((kb * NB + bgB) << 7) + (((hc >> 4) ^ (bgB & 7)) << 4) + (hc & 15);
        b4[nt] = *(const float4*)(g_bI + 4 * j);
    }
    float cst[8], hst[8];
#pragma unroll
    for (int i = 0; i < 8; ++i) { cst[i] = 0.0f; hst[i] = 0.0f; }

    int ph[NST] = {0, 0, 0, 0};
    unsigned mw0 = 0, mw1 = 0;

    // process order p: 0->kt8, 1->kt9 (x blocks), 2..9 -> kt0..kt7 (h blocks)
    auto bulkA_fill = [&](int kt, int s, const __half* hsrc, int t) {
        const __half* asrc = (kt < 8)
            ? (hsrc + ((long)kt * NB + bm) * BK)
            : (g_xB + (((long)t * 2 + (kt - 8)) * NB + bm) * BK);
        bulk_g2s(smb + s * ST_BY, asrc, A_BY, mbb + 8 * s);
    };
    auto bulkB_fill = [&](int kt, int s) {
        bulk_g2s(smb + s * ST_BY + A_BY, g_MB + ((long)kt * NG + bn) * BK, B_BY, mbb + 8 * s);
    };
    // full fill for process index p of step t (B first, poll counter, then A)
    auto fill_p = [&](int p, int t, const __half* hsrc, int srcbuf, unsigned target) {
        const int kt = (p < 2) ? 8 + p : p - 2;
        const int s = (2 * t + p) & 3;
        mbar_expect_tx(mbb + 8 * s, (unsigned)ST_BY);
        bulkB_fill(kt, s);
        if (kt < 8 && t > 0) wait_cnt(&g_hcnt[srcbuf * 8 + kt], target);
        bulkA_fill(kt, s, hsrc, t);
    };

    // prologue: fills p=0,1 of t=0 (x blocks kt8,kt9; stages 0,1; no gating)
    if (tid == 0) {
        mbar_expect_tx(mbb + 0, (unsigned)ST_BY);
        bulkB_fill(8, 0);
        bulkA_fill(8, 0, g_h, 0);
        mbar_expect_tx(mbb + 8, (unsigned)ST_BY);
        bulkB_fill(9, 1);
        bulkA_fill(9, 1, g_h, 0);
    }

    for (int t = 0; t < NT; ++t) {
        const int srcbuf = t & 1;
        const __half* __restrict__ hsrc = g_h + srcbuf * HSZ;
        __half* __restrict__ hdst = g_h + (srcbuf ^ 1) * HSZ;
        const unsigned target = 16u * (unsigned)((t + 1) >> 1);
        const int t2 = 2 * t;

        if ((t & 31) == 0) {
            mw0 = g_maskw[bgA * 16 + (t >> 5)];
            mw1 = g_maskw[bgB * 16 + (t >> 5)];
        }

        float acc[2][4][4];
#pragma unroll
        for (int i = 0; i < 2; ++i)
#pragma unroll
            for (int j = 0; j < 4; ++j)
#pragma unroll
                for (int k = 0; k < 4; ++k) acc[i][j][k] = 0.0f;

        for (int p = 0; p < NKT; ++p) {
            const int s = (t2 + p) & 3;
            if ((p & 1) == 0) {
                // even p: one warp waits, CTA-wide sync, then fills.
                // Stage-reuse safe: sync proves all warps past p-1; fills p+2,p+3
                // target stages of fills p-2,p-1 (already fully consumed).
                if (w == 0) mbar_wait(mbb + 8 * s, (unsigned)ph[s]);
                __syncthreads();
                if (tid == 0) {
                    if (p < 8) {
                        fill_p(p + 2, t, hsrc, srcbuf, target);
                        fill_p(p + 3, t, hsrc, srcbuf, target);
                    } else if (t + 1 < NT) {
                        // p == 8: next step's x-block fills (no counter gating!)
                        const int sA = (t2 + 2) & 3, sB = (t2 + 3) & 3;
                        mbar_expect_tx(mbb + 8 * sA, (unsigned)ST_BY);
                        bulkB_fill(8, sA);
                        bulkA_fill(8, sA, hsrc, t + 1);
                        mbar_expect_tx(mbb + 8 * sB, (unsigned)ST_BY);
                        bulkB_fill(9, sB);
                        bulkA_fill(9, sB, hsrc, t + 1);
                    }
                }
            } else {
                mbar_wait(mbb + 8 * s, (unsigned)ph[s]);  // odd p: per-thread wait
            }
            ph[s] ^= 1;

            const __half* Ab = sh + s * ST_H;
            const __half* arow = Ab + (wm * 32 + g) * BK;
            const __half* brow = Ab + A_H + (wn * 32 + g) * BK;

            // double-buffered fragment pipeline over the 8 chunks
            uint2 fA[2][4], fB[2][4];
            {
                const int o = (g << 4) + c4;  // ch 0: (0^g)<<4 + c4
                fA[0][0] = *(const uint2*)(arow + o);
                fA[0][1] = *(const uint2*)(arow + 1024 + o);
                fA[0][2] = *(const uint2*)(arow + 2048 + o);
                fA[0][3] = *(const uint2*)(arow + 3072 + o);
                fB[0][0] = *(const uint2*)(brow + o);
                fB[0][1] = *(const uint2*)(brow + 1024 + o);
                fB[0][2] = *(const uint2*)(brow + 2048 + o);
                fB[0][3] = *(const uint2*)(brow + 3072 + o);
            }
#pragma unroll
            for (int ch = 0; ch < 8; ++ch) {
                const int cb = ch & 1;
                if (ch < 7) {
                    const int o = (((ch + 1) ^ g) << 4) + c4;
                    uint2* a = fA[cb ^ 1];
                    uint2* b = fB[cb ^ 1];
                    a[0] = *(const uint2*)(arow + o);
                    a[1] = *(const uint2*)(arow + 1024 + o);
                    a[2] = *(const uint2*)(arow + 2048 + o);
                    a[3] = *(const uint2*)(arow + 3072 + o);
                    b[0] = *(const uint2*)(brow + o);
                    b[1] = *(const uint2*)(brow + 1024 + o);
                    b[2] = *(const uint2*)(brow + 2048 + o);
                    b[3] = *(const uint2*)(brow + 3072 + o);
                }
                const uint2* a = fA[cb];
                const uint2* b = fB[cb];
                mma16(acc[0][0], a[0].x, a[1].x, a[0].y, a[1].y, b[0].x, b[0].y);
                mma16(acc[0][1], a[0].x, a[1].x, a[0].y, a[1].y, b[1].x, b[1].y);
                mma16(acc[0][2], a[0].x, a[1].x, a[0].y, a[1].y, b[2].x, b[2].y);
                mma16(acc[0][3], a[0].x, a[1].x, a[0].y, a[1].y, b[3].x, b[3].y);
                mma16(acc[1][0], a[2].x, a[3].x, a[2].y, a[3].y, b[0].x, b[0].y);
                mma16(acc[1][1], a[2].x, a[3].x, a[2].y, a[3].y, b[1].x, b[1].y);
                mma16(acc[1][2], a[2].x, a[3].x, a[2].y, a[3].y, b[2].x, b[2].y);
                mma16(acc[1][3], a[2].x, a[3].x, a[2].y, a[3].y, b[3].x, b[3].y);
            }
        }

        // register-state epilogue (shuffle gate quads)
        const unsigned bit0 = (mw0 >> (t & 31)) & 1u;
        const unsigned bit1 = (mw1 >> (t & 31)) & 1u;
#pragma unroll
        for (int i = 0; i < 8; ++i) {
            const int mt = i >> 2, nt = i & 3;
            float v0 = acc[mt][nt][0], v1 = acc[mt][nt][1];
            float v2 = acc[mt][nt][2], v3 = acc[mt][nt][3];
            float sx = odd ? v0 : v2;
            float sy = odd ? v1 : v3;
            float gx = __shfl_xor_sync(0xffffffffu, sx, 1);
            float gy = __shfl_xor_sync(0xffffffffu, sy, 1);
            float zi, zf, zg, zo;
            if (!odd) { zi = v0; zf = v1; zg = gx; zo = gy; }
            else      { zi = gx; zf = gy; zg = v2; zo = v3; }
            float4 bb = b4[nt];
            zi += bb.x; zf += bb.y; zg += bb.z; zo += bb.w;
            float iv = sigmf(zi), fv = sigmf(zf), gv = tanhfa(zg), ov = sigmf(zo);
            float cn = fv * cst[i] + iv * gv;
            float hn = ov * tanhfa(cn);
            unsigned msk = mt ? bit1 : bit0;
            if (!msk) { cn = cst[i]; hn = hst[i]; }
            cst[i] = cn;
            hst[i] = hn;
            hdst[mt ? hposB[nt] : hposA[nt]] = __float2half_rn(hn);
        }

        // publish our h block (release); next step's x fills already in flight
        __syncthreads();
        if (tid == 0) {
            __threadfence();
            atomicAdd(&g_hcnt[(srcbuf ^ 1) * 8 + kb_own], 1u);
        }
    }

    // final c (fp32) for the MLP head
#pragma unroll
    for (int i = 0; i < 8; ++i) {
        int bg = (i >> 2) ? bgB : bgA;
        g_cf[(long)bg * NH + jj[i & 3]] = cst[i];
    }
    __syncthreads();
    if (tid == 0)
        for (int s = 0; s < NST; ++s) mbar_inval(mbb + 8 * s);
}

// un-permute/un-swizzle final h (buffer 0 after 512 steps) to fp32
__global__ void __launch_bounds__(256) unperm_h() {
    int idx = blockIdx.x * 256 + threadIdx.x; // NB*NH
    int b = idx >> 10, j = idx & 1023;
    int q = (j & ~15) | c_pinv[j & 15];
    int kb = q >> 7, hc = q & 127;
    long off = (((long)kb * NB + b) << 7) + (((hc >> 4) ^ (b & 7)) << 4) + (hc & 15);
    g_hf[idx] = __half2float(g_h[off]);
}

// ---------------- MLP head ----------------
__global__ void __launch_bounds__(256) mlp1_kernel(const float* __restrict__ b1) {
    __shared__ float a_s[64 * 20];
    __shared__ float b_s[16 * 68];
    int tid = threadIdx.x;
    int bn = blockIdx.x * 64, bm = blockIdx.y * 64;
    int ty = tid >> 4, tx = tid & 15;
    float acc[4][4];
#pragma unroll
    for (int i = 0; i < 4; ++i)
#pragma unroll
        for (int j = 0; j < 4; ++j) acc[i][j] = 0.0f;

    for (int kt = 0; kt < 128; ++kt) {
        int k0 = kt * 16;
        {
            int m = tid >> 2, kq = tid & 3;
            int k = k0 + 4 * kq;
            const float* src = (k < NH) ? (g_hf + (long)(bm + m) * NH + k)
                                        : (g_cf + (long)(bm + m) * NH + (k - NH));
            *(float4*)(a_s + m * 20 + 4 * kq) = *(const float4*)src;
        }
        {
            int kr = tid >> 4, cq = tid & 15;
            *(float4*)(b_s + kr * 68 + 4 * cq) =
                *(const float4*)(g_MLP + (long)(k0 + kr) * NH + bn + 4 * cq);
        }
        __syncthreads();
#pragma unroll
        for (int k = 0; k < 16; ++k) {
            float ar[4], br[4];
#pragma unroll
            for (int i = 0; i < 4; ++i) {
                ar[i] = a_s[(4 * ty + i) * 20 + k];
                br[i] = b_s[k * 68 + 4 * tx + i];
            }
#pragma unroll
            for (int i = 0; i < 4; ++i)
#pragma unroll
                for (int j = 0; j < 4; ++j) acc[i][j] += ar[i] * br[j];
        }
        __syncthreads();
    }
#pragma unroll
    for (int i = 0; i < 4; ++i)
#pragma unroll
        for (int j = 0; j < 4; ++j) {
            float v = acc[i][j] + b1[bn + 4 * tx + j];
            v = v > 0.0f ? v : 0.2f * v;
            g_y1[(long)(bm + 4 * ty + i) * NH + bn + 4 * tx + j] = v;
        }
}

__global__ void __launch_bounds__(64) mlp2_kernel(
    const float* __restrict__ W2, const float* __restrict__ b2, float* __restrict__ out) {
    __shared__ float row[NH];
    int bg = blockIdx.x;
    int o = threadIdx.x;
    for (int i = o; i < NH; i += 64) row[i] = g_y1[(long)bg * NH + i];
    __syncthreads();
    float acc = b2[o];
#pragma unroll 8
    for (int k = 0; k < NH; ++k) acc += row[k] * W2[(long)k * NOUT + o];
    out[(long)bg * NOUT + o] = acc;
}

// ---------------- launch ----------------
extern "C" void kernel_launch(void* const* d_in, const int* in_sizes, int n_in,
                              void* d_out, int out_size) {
    const float* x  = (const float*)d_in[0];
    const float* W  = (const float*)d_in[1];
    const float* U  = (const float*)d_in[2];
    const float* b  = (const float*)d_in[3];
    const float* W1 = (const float*)d_in[4];
    const float* b1 = (const float*)d_in[5];
    const float* W2 = (const float*)d_in[6];
    const float* b2 = (const float*)d_in[7];
    float* out = (float*)d_out;

    cudaFuncSetAttribute(lstm_persistent,
                         cudaFuncAttributeMaxDynamicSharedMemorySize, SMEM_BYTES);

    const long WN = (long)10 * NG * 128;
    const long MN = (long)NT * 2 * NB * 8 + (long)2048 * NH + (long)HSZ / 8 + 16;

    // lstm_persistent is the 4th launch (ncu profiles launch index 3)
    mask_kernel<<<(NB * NT * 32) / 256, 256>>>(x);
    prep_weights<<<(int)(WN / 256), 256>>>(W, U, b);
    prep_misc<<<(int)((MN + 255) / 256), 256>>>(x, W1);
    lstm_persistent<<<dim3(NG / BN, NB / BM), 256, SMEM_BYTES>>>();
    unperm_h<<<(NB * NH) / 256, 256>>>();
    mlp1_kernel<<<dim3(NH / 64, NB / 64), 256>>>(b1);
    mlp2_kernel<<<NB, 64>>>(W2, b2, out);
}